// round 14
// baseline (speedup 1.0000x reference)
#include <cuda_runtime.h>
#include <cuda_bf16.h>
#include <cstdint>

// Grouping: out[B,G,H] = sum_{t=0..3} values[4r+t] * feats[row 4r+t, :], r = b*G+g.
// B=8, S=4096, H=1024, G=1024 -> 8192 output rows, 128 MB read + 32 MB write.
// R14: clean load-width experiment (last untested axis). Plain 32B loads
// (ld.global.nc.v4.b64, LDG.256, NO cache-policy hints -- hints were the
// falsified variable in R2/R8), 256-thr CTAs, 2 rows/CTA, each thread owns
// 8 consecutive floats per source row. Halves LDG instruction count and LSU
// dispatch-queue occupancy per byte vs the 16B formulation. If neutral, R1
// stands as the confirmed floor.

static constexpr int NROWS = 8 * 1024;
static constexpr int ROWS_PER_CTA = 2;

struct F8 { float f[8]; };

__device__ __forceinline__ F8 ld32(const float* p) {
    uint64_t a, b, c, d;
    asm volatile("ld.global.nc.v4.b64 {%0,%1,%2,%3}, [%4];"
                 : "=l"(a), "=l"(b), "=l"(c), "=l"(d) : "l"(p));
    F8 r;
    r.f[0] = __uint_as_float((uint32_t)a); r.f[1] = __uint_as_float((uint32_t)(a >> 32));
    r.f[2] = __uint_as_float((uint32_t)b); r.f[3] = __uint_as_float((uint32_t)(b >> 32));
    r.f[4] = __uint_as_float((uint32_t)c); r.f[5] = __uint_as_float((uint32_t)(c >> 32));
    r.f[6] = __uint_as_float((uint32_t)d); r.f[7] = __uint_as_float((uint32_t)(d >> 32));
    return r;
}

__global__ __launch_bounds__(256)
void grouping_kernel(const float* __restrict__ feats,
                     const float* __restrict__ values,
                     float4* __restrict__ out) {
    const int r = blockIdx.x * ROWS_PER_CTA + (threadIdx.x >> 7);  // output row
    const int c = threadIdx.x & 127;                               // owns floats [8c, 8c+8)

    const float v0 = __ldg(&values[4 * r + 0]);
    const float v1 = __ldg(&values[4 * r + 1]);
    const float v2 = __ldg(&values[4 * r + 2]);
    const float v3 = __ldg(&values[4 * r + 3]);

    const float* p = feats + (size_t)r * 4096 + c * 8;  // 4 source rows of 1024 floats
    // 4 independent 32B loads (LDG.256), plain policy
    const F8 a = ld32(p);
    const F8 b = ld32(p + 1024);
    const F8 d = ld32(p + 2048);
    const F8 e = ld32(p + 3072);

    float o[8];
#pragma unroll
    for (int i = 0; i < 8; i++)
        o[i] = v0 * a.f[i] + v1 * b.f[i] + v2 * d.f[i] + v3 * e.f[i];

    float4* op = out + (size_t)r * 256 + c * 2;
    op[0] = make_float4(o[0], o[1], o[2], o[3]);
    op[1] = make_float4(o[4], o[5], o[6], o[7]);
}

extern "C" void kernel_launch(void* const* d_in, const int* in_sizes, int n_in,
                              void* d_out, int out_size) {
    // metadata order: feats(f32), indices(int), values(f32), num_groups
    const float* feats  = (const float*)d_in[0];
    const float* values = (const float*)d_in[2];
    float4*      out    = (float4*)d_out;

    grouping_kernel<<<NROWS / ROWS_PER_CTA, 256>>>(feats, values, out);
}

// round 16
// speedup vs baseline: 1.2437x; 1.2437x over previous
#include <cuda_runtime.h>
#include <cuda_bf16.h>

// Grouping: out[B,G,H] = sum_{t=0..3} values[(b*G+g)*4+t] * feats[b, g*4+t, :]
// B=8, S=4096, H=1024, G=1024, TOKENS_PER_GROUP=4 -> 8192 output rows.
//
// FINAL KERNEL — confirmed hardware floor over 9 experiments.
// Plain LDG.128 x4 per thread, regs=32, default L2 policy, 256 thr/CTA,
// 1 output row per CTA. Best timed result 29.184 us; kernel 24.2-25.3 us at
// 6.0-6.2 TB/s HBM (~77% of spec = mixed 4:1 read/write stream ceiling).
// Traffic (128 MB read + 32 MB write) is irreducible.
// Falsified levers, each in a dedicated round:
//   - __ldcs / evict_first / evict_last policies (R2 -4%, R8 -18%)
//   - persistent grid + software pipeline at regs>32 (R4 -3%)
//   - 1024-thread CTAs + __stcs (R5 neutral)
//   - inter-replay L2 residency via evict_last (R8: no timed benefit)
//   - values float4 packing (R9/R11 neutral)
//   - 32B LDG.256 loads (R14: kernel-time neutral, timed replays -24%)
// TMA == LDG at the LTS cap; DRAM is the binding pipe; tensor pipes irrelevant
// (arithmetic intensity 0.2 FLOP/B).

static constexpr int H_VEC = 1024 / 4;  // 256 float4 per row

__global__ __launch_bounds__(256, 8)
void grouping_kernel(const float4* __restrict__ feats,
                     const float* __restrict__ values,
                     float4* __restrict__ out) {
    const int r = blockIdx.x;            // output row: b*G + g
    const int c = threadIdx.x;           // float4 column, 0..255

    const size_t src_base = (size_t)r * 4 * H_VEC;
    const float v0 = __ldg(&values[4 * r + 0]);
    const float v1 = __ldg(&values[4 * r + 1]);
    const float v2 = __ldg(&values[4 * r + 2]);
    const float v3 = __ldg(&values[4 * r + 3]);

    // 4 independent 16B loads -> MLP=4 per thread, 64 warps/SM aggregate
    const float4 a = __ldg(&feats[src_base + 0 * H_VEC + c]);
    const float4 b = __ldg(&feats[src_base + 1 * H_VEC + c]);
    const float4 d = __ldg(&feats[src_base + 2 * H_VEC + c]);
    const float4 e = __ldg(&feats[src_base + 3 * H_VEC + c]);

    float4 o;
    o.x = v0 * a.x + v1 * b.x + v2 * d.x + v3 * e.x;
    o.y = v0 * a.y + v1 * b.y + v2 * d.y + v3 * e.y;
    o.z = v0 * a.z + v1 * b.z + v2 * d.z + v3 * e.z;
    o.w = v0 * a.w + v1 * b.w + v2 * d.w + v3 * e.w;

    out[(size_t)r * H_VEC + c] = o;
}

extern "C" void kernel_launch(void* const* d_in, const int* in_sizes, int n_in,
                              void* d_out, int out_size) {
    // metadata order: feats(f32), indices(int), values(f32), num_groups
    const float4* feats  = (const float4*)d_in[0];
    const float*  values = (const float*)d_in[2];
    float4*       out    = (float4*)d_out;

    const int B = 8, G = 1024;
    grouping_kernel<<<B * G, 256>>>(feats, values, out);
}